// round 4
// baseline (speedup 1.0000x reference)
#include <cuda_runtime.h>
#include <cuda_bf16.h>
#include <cstdint>

#define C_IN    64
#define K_OUT   64
#define H_IN    130
#define W_IN    130
#define P_TILES 16384
#define H_OUT   128

// Scratch (device globals: allocation-free rule). V/U pre-split to bf16 hi/lo.
__device__ __nv_bfloat16 g_Uh[36 * K_OUT * C_IN];            // [e][k][c]
__device__ __nv_bfloat16 g_Ul[36 * K_OUT * C_IN];
__device__ __nv_bfloat16 g_Vh[(size_t)36 * P_TILES * C_IN];  // [e][p][c]  75.5 MB
__device__ __nv_bfloat16 g_Vl[(size_t)36 * P_TILES * C_IN];  // 75.5 MB

__device__ const float d_ATx[24] = {
    1.f, 1.f,  1.f, 1.f,  1.f, 0.f,
    0.f, 1.f, -1.f, 2.f, -2.f, 0.f,
    0.f, 1.f,  1.f, 4.f,  4.f, 0.f,
    0.f, 1.f, -1.f, 8.f, -8.f, 1.f};

__device__ __forceinline__ uint32_t smem_u32(const void* p) {
    uint32_t a;
    asm("{ .reg .u64 t; cvta.to.shared.u64 t, %1; cvt.u32.u64 %0, t; }"
        : "=r"(a) : "l"(p));
    return a;
}

#define LDSM4(r, a)                                                          \
    asm volatile("ldmatrix.sync.aligned.m8n8.x4.shared.b16 {%0,%1,%2,%3}, [%4];" \
                 : "=r"((r)[0]), "=r"((r)[1]), "=r"((r)[2]), "=r"((r)[3])    \
                 : "r"(a))

#define MMA_BF16(c, a, b0, b1)                                               \
    asm volatile("mma.sync.aligned.m16n8k16.row.col.f32.bf16.bf16.f32 "      \
                 "{%0,%1,%2,%3},{%4,%5,%6,%7},{%8,%9},{%0,%1,%2,%3};"        \
                 : "+f"((c)[0]), "+f"((c)[1]), "+f"((c)[2]), "+f"((c)[3])    \
                 : "r"((a)[0]), "r"((a)[1]), "r"((a)[2]), "r"((a)[3]),       \
                   "r"(b0), "r"(b1))

__device__ __forceinline__ void cp16(uint32_t dst, const void* src) {
    asm volatile("cp.async.cg.shared.global [%0], [%1], 16;" :: "r"(dst), "l"(src));
}
#define CP_COMMIT() asm volatile("cp.async.commit_group;" ::: "memory")
#define CP_WAIT1()  asm volatile("cp.async.wait_group 1;" ::: "memory")

// ---------------------------------------------------------------------------
// Kernel 1: filter transform -> g_Uh/g_Ul bf16 [e][k][c]
// ---------------------------------------------------------------------------
__global__ void filter_transform(const float* __restrict__ w) {
    int gid = blockIdx.x * blockDim.x + threadIdx.x;
    int c = gid & 63;
    int k = gid >> 6;

    constexpr float G[6][3] = {
        { 0.25f,     0.f,       0.f     },
        {-1.f/6.f,  -1.f/6.f,  -1.f/6.f },
        {-1.f/6.f,   1.f/6.f,  -1.f/6.f },
        { 1.f/24.f,  1.f/12.f,  1.f/6.f },
        { 1.f/24.f, -1.f/12.f,  1.f/6.f },
        { 0.f,       0.f,       1.f     }};

    float wv[3][3];
    const float* wp = w + (k * C_IN + c) * 9;
#pragma unroll
    for (int i = 0; i < 3; i++)
#pragma unroll
        for (int j = 0; j < 3; j++) wv[i][j] = wp[i * 3 + j];

    float gw[6][3];
#pragma unroll
    for (int a = 0; a < 6; a++)
#pragma unroll
        for (int j = 0; j < 3; j++)
            gw[a][j] = G[a][0] * wv[0][j] + G[a][1] * wv[1][j] + G[a][2] * wv[2][j];

#pragma unroll
    for (int a = 0; a < 6; a++)
#pragma unroll
        for (int b = 0; b < 6; b++) {
            float u = gw[a][0] * G[b][0] + gw[a][1] * G[b][1] + gw[a][2] * G[b][2];
            int idx = ((a * 6 + b) * K_OUT + k) * C_IN + c;
            __nv_bfloat16 h = __float2bfloat16_rn(u);
            g_Uh[idx] = h;
            g_Ul[idx] = __float2bfloat16_rn(u - __bfloat162float(h));
        }
}

// ---------------------------------------------------------------------------
// Kernel 2: input transform -> g_Vh/g_Vl bf16 [e][p][c]
// ---------------------------------------------------------------------------
__global__ __launch_bounds__(256) void input_transform2(const float* __restrict__ x) {
    __shared__ float Vs[36][16][17];   // [e][c_l][s_l]

    int tid = threadIdx.x;
    int nt = blockIdx.x;               // 0..511
    int n = nt >> 5, t = nt & 31;
    int sh = blockIdx.y;               // 0..1
    int ch = blockIdx.z;               // 0..3

    int s_l = tid & 15, c_l = tid >> 4;
    int c = ch * 16 + c_l;
    int s = sh * 16 + s_l;

    const float* base = x + ((size_t)(n * C_IN + c) * H_IN + t * 4) * W_IN + s * 4;

    float d[6][6];
#pragma unroll
    for (int i = 0; i < 6; i++)
#pragma unroll
        for (int j = 0; j < 6; j++) d[i][j] = base[i * W_IN + j];

    constexpr float BT[6][6] = {
        {4.f, 0.f, -5.f,  0.f, 1.f, 0.f},
        {0.f,-4.f, -4.f,  1.f, 1.f, 0.f},
        {0.f, 4.f, -4.f, -1.f, 1.f, 0.f},
        {0.f,-2.f, -1.f,  2.f, 1.f, 0.f},
        {0.f, 2.f, -1.f, -2.f, 1.f, 0.f},
        {0.f, 4.f,  0.f, -5.f, 0.f, 1.f}};

    float t1[6][6];
#pragma unroll
    for (int a = 0; a < 6; a++)
#pragma unroll
        for (int j = 0; j < 6; j++) {
            float acc = 0.f;
#pragma unroll
            for (int i = 0; i < 6; i++) acc += BT[a][i] * d[i][j];
            t1[a][j] = acc;
        }
#pragma unroll
    for (int a = 0; a < 6; a++)
#pragma unroll
        for (int b = 0; b < 6; b++) {
            float acc = 0.f;
#pragma unroll
            for (int j = 0; j < 6; j++) acc += t1[a][j] * BT[b][j];
            Vs[a * 6 + b][c_l][s_l] = acc;
        }
    __syncthreads();

    // write phase: 128 threads -> hi planes, 128 -> lo planes, bf162 stores
    int half = tid >> 7;
    int t2 = tid & 127;
    int c2 = t2 & 7;          // c-pair within 16-c chunk
    int s_w = t2 >> 3;        // 0..15
    int c0 = c2 * 2;
    size_t p = (size_t)(n * 1024 + t * 32 + sh * 16) + s_w;

    __nv_bfloat162* dst = half ? (__nv_bfloat162*)g_Vl : (__nv_bfloat162*)g_Vh;
    size_t base2 = p * 32 + ch * 8 + c2;   // bf162 index within plane stride P*32

#pragma unroll
    for (int e = 0; e < 36; e++) {
        float v0 = Vs[e][c0][s_w], v1 = Vs[e][c0 + 1][s_w];
        __nv_bfloat162 o;
        if (half == 0) {
            o = __floats2bfloat162_rn(v0, v1);
        } else {
            float h0 = __bfloat162float(__float2bfloat16_rn(v0));
            float h1 = __bfloat162float(__float2bfloat16_rn(v1));
            o = __floats2bfloat162_rn(v0 - h0, v1 - h1);
        }
        dst[(size_t)e * P_TILES * 32 + base2] = o;
    }
}

// ---------------------------------------------------------------------------
// Kernel 3: fused GEMM + output transform.
// CTA = one (n,t) tile-row: 32 p x 64 k, loop over all 36 e=(a,b).
// smem: Y accumulator 8448 float4 (135168 B) + 3 stages of 24576 B
//   stage: Vh[32x128B] Vl Uh[64x128B] Ul  (ldsm XOR-swizzled rows)
// ---------------------------------------------------------------------------
#define YF4        8448         /* 4x * (64k*33 + 32s max) */
#define SM_STAGE   135168u
#define STAGE_SZ   24576u
#define FUSED_SMEM (135168u + 3u * 24576u)   /* 208896 B */

__device__ __forceinline__ void issue_e(int e, uint32_t stBase, int tid, size_t p0) {
    int r = tid >> 3, c8 = tid & 7;
    uint32_t swc = (uint32_t)((c8 ^ (r & 7)) << 4);
    const __nv_bfloat16* vh = g_Vh + ((size_t)e * P_TILES + p0 + r) * 64 + c8 * 8;
    const __nv_bfloat16* vl = g_Vl + ((size_t)e * P_TILES + p0 + r) * 64 + c8 * 8;
    cp16(stBase + (uint32_t)(r * 128) + swc, vh);
    cp16(stBase + 4096u + (uint32_t)(r * 128) + swc, vl);
#pragma unroll
    for (int i = 0; i < 2; i++) {
        int ru = r + i * 32;
        uint32_t swu = (uint32_t)((c8 ^ (ru & 7)) << 4);
        cp16(stBase + 8192u + (uint32_t)(ru * 128) + swu,
             g_Uh + (size_t)e * 4096 + ru * 64 + c8 * 8);
        cp16(stBase + 16384u + (uint32_t)(ru * 128) + swu,
             g_Ul + (size_t)e * 4096 + ru * 64 + c8 * 8);
    }
}

__global__ __launch_bounds__(256, 1) void winograd_fused(float* __restrict__ out) {
    extern __shared__ __align__(16) char smem[];
    const uint32_t sb = smem_u32(smem);
    const int tid = threadIdx.x;
    const int lane = tid & 31;
    const int wid = tid >> 5;
    const int wm = wid & 1;        // p half (16)
    const int wn = wid >> 1;       // k quarter (16)
    const int bx = blockIdx.x;     // = n*32 + t
    const int n = bx >> 5, t = bx & 31;
    const size_t p0 = (size_t)bx * 32;

    float4* Y4 = (float4*)smem;
#pragma unroll 4
    for (int i = tid; i < YF4; i += 256)
        Y4[i] = make_float4(0.f, 0.f, 0.f, 0.f);

    // prologue: stages 0,1
    issue_e(0, sb + SM_STAGE + 0 * STAGE_SZ, tid, p0); CP_COMMIT();
    issue_e(1, sb + SM_STAGE + 1 * STAGE_SZ, tid, p0); CP_COMMIT();

    constexpr float ATC[4][6] = {
        {1.f, 1.f,  1.f, 1.f,  1.f, 0.f},
        {0.f, 1.f, -1.f, 2.f, -2.f, 0.f},
        {0.f, 1.f,  1.f, 4.f,  4.f, 0.f},
        {0.f, 1.f, -1.f, 8.f, -8.f, 1.f}};

    for (int a = 0; a < 6; a++) {
        float Z[2][4][4];
#pragma unroll
        for (int ni = 0; ni < 2; ni++)
#pragma unroll
            for (int q = 0; q < 4; q++)
#pragma unroll
                for (int y = 0; y < 4; y++) Z[ni][q][y] = 0.f;

#pragma unroll
        for (int b = 0; b < 6; b++) {
            const int eg = a * 6 + b;
            CP_WAIT1();
            __syncthreads();
            const int ep = eg + 2;
            if (ep < 36)
                issue_e(ep, sb + SM_STAGE + (uint32_t)((b + 2) % 3) * STAGE_SZ, tid, p0);
            CP_COMMIT();

            const uint32_t st = sb + SM_STAGE + (uint32_t)(b % 3) * STAGE_SZ;

            float acc[2][4];
#pragma unroll
            for (int ni = 0; ni < 2; ni++)
#pragma unroll
                for (int q = 0; q < 4; q++) acc[ni][q] = 0.f;

#pragma unroll
            for (int ks = 0; ks < 4; ks++) {
                uint32_t Ah[4], Al[4], Bh[4], Bl[4];
                int rowA = wm * 16 + (lane & 15);
                int colA = (ks * 2 + (lane >> 4)) ^ (rowA & 7);
                uint32_t aA = st + (uint32_t)(rowA * 128 + colA * 16);
                LDSM4(Ah, aA);
                LDSM4(Al, aA + 4096u);
                int rowB = wn * 16 + (lane & 15);
                int colB = (ks * 2 + (lane >> 4)) ^ (rowB & 7);
                uint32_t aB = st + 8192u + (uint32_t)(rowB * 128 + colB * 16);
                LDSM4(Bh, aB);
                LDSM4(Bl, aB + 8192u);
#pragma unroll
                for (int ni = 0; ni < 2; ni++) {
                    MMA_BF16(acc[ni], Ah, Bh[ni], Bh[ni + 2]);   // hi*hi
                    MMA_BF16(acc[ni], Ah, Bl[ni], Bl[ni + 2]);   // hi*lo
                    MMA_BF16(acc[ni], Al, Bh[ni], Bh[ni + 2]);   // lo*hi
                }
            }
            // Z[y] += AT[y][b] * M
#pragma unroll
            for (int ni = 0; ni < 2; ni++)
#pragma unroll
                for (int q = 0; q < 4; q++)
#pragma unroll
                    for (int y = 0; y < 4; y++)
                        Z[ni][q][y] += ATC[y][b] * acc[ni][q];
        }

        // Y[x][y] += AT[x][a] * Z[y]   (smem RMW, disjoint per thread)
        float cx0 = d_ATx[a], cx1 = d_ATx[6 + a], cx2 = d_ATx[12 + a], cx3 = d_ATx[18 + a];
#pragma unroll
        for (int ni = 0; ni < 2; ni++)
#pragma unroll
            for (int q = 0; q < 4; q++) {
                int pl = wm * 16 + (lane >> 2) + ((q >> 1) << 3);
                int k  = wn * 16 + ni * 8 + ((lane & 3) << 1) + (q & 1);
                int base = k * 33 + pl;
                const float* z = Z[ni][q];
#pragma unroll
                for (int x = 0; x < 4; x++) {
                    float cx = (x == 0) ? cx0 : (x == 1) ? cx1 : (x == 2) ? cx2 : cx3;
                    float4 v = Y4[x * 2112 + base];
                    v.x += cx * z[0]; v.y += cx * z[1];
                    v.z += cx * z[2]; v.w += cx * z[3];
                    Y4[x * 2112 + base] = v;
                }
            }
    }

    __syncthreads();
    // write out: rows (k,x), 32 lanes * float4 = 512 B coalesced
#pragma unroll
    for (int kk = 0; kk < 8; kk++) {
        int k = wid * 8 + kk;
#pragma unroll
        for (int x = 0; x < 4; x++) {
            float4 v = Y4[x * 2112 + k * 33 + lane];
            *(float4*)&out[(((size_t)(n * K_OUT + k) * H_OUT) + t * 4 + x) * H_OUT + lane * 4] = v;
        }
    }
}

// ---------------------------------------------------------------------------
extern "C" void kernel_launch(void* const* d_in, const int* in_sizes, int n_in,
                              void* d_out, int out_size) {
    const float* x = (const float*)d_in[0];   // (16,64,130,130)
    const float* w = (const float*)d_in[1];   // (64,64,3,3)
    float* out = (float*)d_out;               // (16,64,128,128)

    cudaFuncSetAttribute(winograd_fused,
                         cudaFuncAttributeMaxDynamicSharedMemorySize, FUSED_SMEM);

    filter_transform<<<16, 256>>>(w);
    input_transform2<<<dim3(512, 2, 4), 256>>>(x);
    winograd_fused<<<512, 256, FUSED_SMEM>>>(out);
}

// round 5
// speedup vs baseline: 1.1856x; 1.1856x over previous
#include <cuda_runtime.h>
#include <cuda_bf16.h>
#include <cstdint>

#define C_IN    64
#define K_OUT   64
#define H_IN    130
#define W_IN    130
#define P_TILES 16384
#define H_OUT   128

// Scratch (device globals: allocation-free rule). V/U pre-split to bf16 hi/lo.
__device__ __nv_bfloat16 g_Uh[36 * K_OUT * C_IN];            // [e][k][c]
__device__ __nv_bfloat16 g_Ul[36 * K_OUT * C_IN];
__device__ __nv_bfloat16 g_Vh[(size_t)36 * P_TILES * C_IN];  // [e][p][c]  75.5 MB
__device__ __nv_bfloat16 g_Vl[(size_t)36 * P_TILES * C_IN];  // 75.5 MB

__device__ const float d_ATx[24] = {
    1.f, 1.f,  1.f, 1.f,  1.f, 0.f,
    0.f, 1.f, -1.f, 2.f, -2.f, 0.f,
    0.f, 1.f,  1.f, 4.f,  4.f, 0.f,
    0.f, 1.f, -1.f, 8.f, -8.f, 1.f};

__device__ __forceinline__ uint32_t smem_u32(const void* p) {
    uint32_t a;
    asm("{ .reg .u64 t; cvta.to.shared.u64 t, %1; cvt.u32.u64 %0, t; }"
        : "=r"(a) : "l"(p));
    return a;
}

#define LDSM4(r, a)                                                          \
    asm volatile("ldmatrix.sync.aligned.m8n8.x4.shared.b16 {%0,%1,%2,%3}, [%4];" \
                 : "=r"((r)[0]), "=r"((r)[1]), "=r"((r)[2]), "=r"((r)[3])    \
                 : "r"(a))

#define MMA_BF16(c, a, b0, b1)                                               \
    asm volatile("mma.sync.aligned.m16n8k16.row.col.f32.bf16.bf16.f32 "      \
                 "{%0,%1,%2,%3},{%4,%5,%6,%7},{%8,%9},{%0,%1,%2,%3};"        \
                 : "+f"((c)[0]), "+f"((c)[1]), "+f"((c)[2]), "+f"((c)[3])    \
                 : "r"((a)[0]), "r"((a)[1]), "r"((a)[2]), "r"((a)[3]),       \
                   "r"(b0), "r"(b1))

__device__ __forceinline__ void cp16(uint32_t dst, const void* src) {
    asm volatile("cp.async.cg.shared.global [%0], [%1], 16;" :: "r"(dst), "l"(src));
}
#define CP_COMMIT() asm volatile("cp.async.commit_group;" ::: "memory")
#define CP_WAIT(n)  asm volatile("cp.async.wait_group %0;" :: "n"(n) : "memory")

// ---------------------------------------------------------------------------
// Kernel 1: filter transform -> g_Uh/g_Ul bf16 [e][k][c]
// ---------------------------------------------------------------------------
__global__ void filter_transform(const float* __restrict__ w) {
    int c = threadIdx.x;        // 64 threads
    int k = blockIdx.x;         // 64 blocks

    constexpr float G[6][3] = {
        { 0.25f,     0.f,       0.f     },
        {-1.f/6.f,  -1.f/6.f,  -1.f/6.f },
        {-1.f/6.f,   1.f/6.f,  -1.f/6.f },
        { 1.f/24.f,  1.f/12.f,  1.f/6.f },
        { 1.f/24.f, -1.f/12.f,  1.f/6.f },
        { 0.f,       0.f,       1.f     }};

    float wv[3][3];
    const float* wp = w + (k * C_IN + c) * 9;
#pragma unroll
    for (int i = 0; i < 3; i++)
#pragma unroll
        for (int j = 0; j < 3; j++) wv[i][j] = wp[i * 3 + j];

    float gw[6][3];
#pragma unroll
    for (int a = 0; a < 6; a++)
#pragma unroll
        for (int j = 0; j < 3; j++)
            gw[a][j] = G[a][0] * wv[0][j] + G[a][1] * wv[1][j] + G[a][2] * wv[2][j];

#pragma unroll
    for (int a = 0; a < 6; a++)
#pragma unroll
        for (int b = 0; b < 6; b++) {
            float u = gw[a][0] * G[b][0] + gw[a][1] * G[b][1] + gw[a][2] * G[b][2];
            int idx = ((a * 6 + b) * K_OUT + k) * C_IN + c;
            __nv_bfloat16 h = __float2bfloat16_rn(u);
            g_Uh[idx] = h;
            g_Ul[idx] = __float2bfloat16_rn(u - __bfloat162float(h));
        }
}

// ---------------------------------------------------------------------------
// Kernel 2: input transform -> g_Vh/g_Vl bf16 [e][p][c]
// ---------------------------------------------------------------------------
__global__ __launch_bounds__(256) void input_transform2(const float* __restrict__ x) {
    __shared__ float Vs[36][16][17];   // [e][c_l][s_l]

    int tid = threadIdx.x;
    int nt = blockIdx.x;               // 0..511
    int n = nt >> 5, t = nt & 31;
    int sh = blockIdx.y;               // 0..1
    int ch = blockIdx.z;               // 0..3

    int s_l = tid & 15, c_l = tid >> 4;
    int c = ch * 16 + c_l;
    int s = sh * 16 + s_l;

    const float* base = x + ((size_t)(n * C_IN + c) * H_IN + t * 4) * W_IN + s * 4;

    float d[6][6];
#pragma unroll
    for (int i = 0; i < 6; i++)
#pragma unroll
        for (int j = 0; j < 6; j++) d[i][j] = base[i * W_IN + j];

    constexpr float BT[6][6] = {
        {4.f, 0.f, -5.f,  0.f, 1.f, 0.f},
        {0.f,-4.f, -4.f,  1.f, 1.f, 0.f},
        {0.f, 4.f, -4.f, -1.f, 1.f, 0.f},
        {0.f,-2.f, -1.f,  2.f, 1.f, 0.f},
        {0.f, 2.f, -1.f, -2.f, 1.f, 0.f},
        {0.f, 4.f,  0.f, -5.f, 0.f, 1.f}};

    float t1[6][6];
#pragma unroll
    for (int a = 0; a < 6; a++)
#pragma unroll
        for (int j = 0; j < 6; j++) {
            float acc = 0.f;
#pragma unroll
            for (int i = 0; i < 6; i++) acc += BT[a][i] * d[i][j];
            t1[a][j] = acc;
        }
#pragma unroll
    for (int a = 0; a < 6; a++)
#pragma unroll
        for (int b = 0; b < 6; b++) {
            float acc = 0.f;
#pragma unroll
            for (int j = 0; j < 6; j++) acc += t1[a][j] * BT[b][j];
            Vs[a * 6 + b][c_l][s_l] = acc;
        }
    __syncthreads();

    // write phase: 128 threads -> hi planes, 128 -> lo planes, bf162 stores
    int half = tid >> 7;
    int t2 = tid & 127;
    int c2 = t2 & 7;          // c-pair within 16-c chunk
    int s_w = t2 >> 3;        // 0..15
    int c0 = c2 * 2;
    size_t p = (size_t)(n * 1024 + t * 32 + sh * 16) + s_w;

    __nv_bfloat162* dst = half ? (__nv_bfloat162*)g_Vl : (__nv_bfloat162*)g_Vh;
    size_t base2 = p * 32 + ch * 8 + c2;   // bf162 index within plane stride P*32

#pragma unroll
    for (int e = 0; e < 36; e++) {
        float v0 = Vs[e][c0][s_w], v1 = Vs[e][c0 + 1][s_w];
        __nv_bfloat162 o;
        if (half == 0) {
            o = __floats2bfloat162_rn(v0, v1);
        } else {
            float h0 = __bfloat162float(__float2bfloat16_rn(v0));
            float h1 = __bfloat162float(__float2bfloat16_rn(v1));
            o = __floats2bfloat162_rn(v0 - h0, v1 - h1);
        }
        dst[(size_t)e * P_TILES * 32 + base2] = o;
    }
}

// ---------------------------------------------------------------------------
// Kernel 3: fused GEMM + output transform, register-resident Y.
// CTA = one (n,t) tile-row: 32 p x 64 k, loop over 36 e = 6a x 6b.
// smem: 6 stages x 24576 B  (Vh 4K | Vl 4K | Uh 8K | Ul 8K, ldsm-swizzled)
// ---------------------------------------------------------------------------
#define STAGE_SZ   24576u
#define NSTAGE     6
#define FUSED_SMEM (6u * 24576u)   /* 147456 B */

__device__ __forceinline__ void issue_e(int e, uint32_t stBase, int tid, size_t p0) {
    int r = tid >> 3, c8 = tid & 7;
    uint32_t swc = (uint32_t)((c8 ^ (r & 7)) << 4);
    const __nv_bfloat16* vh = g_Vh + ((size_t)e * P_TILES + p0 + r) * 64 + c8 * 8;
    const __nv_bfloat16* vl = g_Vl + ((size_t)e * P_TILES + p0 + r) * 64 + c8 * 8;
    cp16(stBase + (uint32_t)(r * 128) + swc, vh);
    cp16(stBase + 4096u + (uint32_t)(r * 128) + swc, vl);
#pragma unroll
    for (int i = 0; i < 2; i++) {
        int ru = r + i * 32;
        uint32_t swu = (uint32_t)((c8 ^ (ru & 7)) << 4);
        cp16(stBase + 8192u + (uint32_t)(ru * 128) + swu,
             g_Uh + (size_t)e * 4096 + ru * 64 + c8 * 8);
        cp16(stBase + 16384u + (uint32_t)(ru * 128) + swu,
             g_Ul + (size_t)e * 4096 + ru * 64 + c8 * 8);
    }
}

__global__ __launch_bounds__(256, 1) void winograd_fused(float* __restrict__ out) {
    extern __shared__ __align__(16) char smem[];
    const uint32_t sb = smem_u32(smem);
    const int tid = threadIdx.x;
    const int lane = tid & 31;
    const int wid = tid >> 5;
    const int wm = wid & 1;        // p half (16)
    const int wn = wid >> 1;       // k quarter (16)
    const int bx = blockIdx.x;     // = n*32 + t
    const int n = bx >> 5, t = bx & 31;
    const size_t p0 = (size_t)bx * 32;

    // register-resident output accumulator: Y[x][ni][q][y]
    float Y[4][2][4][4];
#pragma unroll
    for (int x = 0; x < 4; x++)
#pragma unroll
        for (int ni = 0; ni < 2; ni++)
#pragma unroll
            for (int q = 0; q < 4; q++)
#pragma unroll
                for (int y = 0; y < 4; y++) Y[x][ni][q][y] = 0.f;

    // prologue: fill 5 stages
#pragma unroll
    for (int s = 0; s < NSTAGE - 1; s++) {
        issue_e(s, sb + (uint32_t)s * STAGE_SZ, tid, p0);
        CP_COMMIT();
    }

    constexpr float ATC[4][6] = {
        {1.f, 1.f,  1.f, 1.f,  1.f, 0.f},
        {0.f, 1.f, -1.f, 2.f, -2.f, 0.f},
        {0.f, 1.f,  1.f, 4.f,  4.f, 0.f},
        {0.f, 1.f, -1.f, 8.f, -8.f, 1.f}};

    for (int a = 0; a < 6; a++) {          // runtime loop (code size)
        float Z[2][4][4];
#pragma unroll
        for (int ni = 0; ni < 2; ni++)
#pragma unroll
            for (int q = 0; q < 4; q++)
#pragma unroll
                for (int y = 0; y < 4; y++) Z[ni][q][y] = 0.f;

#pragma unroll
        for (int b = 0; b < 6; b++) {      // stage buffer index == b
            CP_WAIT(NSTAGE - 2);
            __syncthreads();
            const int ep = a * 6 + b + NSTAGE - 1;
            if (ep < 36)
                issue_e(ep, sb + (uint32_t)((b + NSTAGE - 1) % NSTAGE) * STAGE_SZ, tid, p0);
            CP_COMMIT();

            const uint32_t st = sb + (uint32_t)b * STAGE_SZ;

            float acc[2][4];
#pragma unroll
            for (int ni = 0; ni < 2; ni++)
#pragma unroll
                for (int q = 0; q < 4; q++) acc[ni][q] = 0.f;

#pragma unroll
            for (int ks = 0; ks < 4; ks++) {
                uint32_t Ah[4], Al[4], Bh[4], Bl[4];
                int rowA = wm * 16 + (lane & 15);
                int colA = (ks * 2 + (lane >> 4)) ^ (rowA & 7);
                uint32_t aA = st + (uint32_t)(rowA * 128 + colA * 16);
                LDSM4(Ah, aA);
                LDSM4(Al, aA + 4096u);
                int rowB = wn * 16 + (lane & 15);
                int colB = (ks * 2 + (lane >> 4)) ^ (rowB & 7);
                uint32_t aB = st + 8192u + (uint32_t)(rowB * 128 + colB * 16);
                LDSM4(Bh, aB);
                LDSM4(Bl, aB + 8192u);
#pragma unroll
                for (int ni = 0; ni < 2; ni++) {
                    MMA_BF16(acc[ni], Ah, Bh[ni], Bh[ni + 2]);   // hi*hi
                    MMA_BF16(acc[ni], Ah, Bl[ni], Bl[ni + 2]);   // hi*lo
                    MMA_BF16(acc[ni], Al, Bh[ni], Bh[ni + 2]);   // lo*hi
                }
            }
            // Z[y] += AT[y][b] * M
#pragma unroll
            for (int ni = 0; ni < 2; ni++)
#pragma unroll
                for (int q = 0; q < 4; q++)
#pragma unroll
                    for (int y = 0; y < 4; y++)
                        Z[ni][q][y] += ATC[y][b] * acc[ni][q];
        }

        // Y[x] += AT[x][a] * Z   (pure register FFMA)
        float cx0 = d_ATx[a], cx1 = d_ATx[6 + a], cx2 = d_ATx[12 + a], cx3 = d_ATx[18 + a];
#pragma unroll
        for (int ni = 0; ni < 2; ni++)
#pragma unroll
            for (int q = 0; q < 4; q++)
#pragma unroll
                for (int y = 0; y < 4; y++) {
                    float z = Z[ni][q][y];
                    Y[0][ni][q][y] += cx0 * z;
                    Y[1][ni][q][y] += cx1 * z;
                    Y[2][ni][q][y] += cx2 * z;
                    Y[3][ni][q][y] += cx3 * z;
                }
    }

    // epilogue: write straight from registers (float4 per (x,ni,q))
#pragma unroll
    for (int ni = 0; ni < 2; ni++)
#pragma unroll
        for (int q = 0; q < 4; q++) {
            int k  = wn * 16 + ni * 8 + ((lane & 3) << 1) + (q & 1);
            int pl = wm * 16 + (lane >> 2) + ((q >> 1) << 3);
#pragma unroll
            for (int x = 0; x < 4; x++) {
                float4 v = make_float4(Y[x][ni][q][0], Y[x][ni][q][1],
                                       Y[x][ni][q][2], Y[x][ni][q][3]);
                *(float4*)&out[(((size_t)(n * K_OUT + k) * H_OUT) + t * 4 + x) * H_OUT + pl * 4] = v;
            }
        }
}

// ---------------------------------------------------------------------------
extern "C" void kernel_launch(void* const* d_in, const int* in_sizes, int n_in,
                              void* d_out, int out_size) {
    const float* x = (const float*)d_in[0];   // (16,64,130,130)
    const float* w = (const float*)d_in[1];   // (64,64,3,3)
    float* out = (float*)d_out;               // (16,64,128,128)

    cudaFuncSetAttribute(winograd_fused,
                         cudaFuncAttributeMaxDynamicSharedMemorySize, FUSED_SMEM);

    filter_transform<<<64, 64>>>(w);
    input_transform2<<<dim3(512, 2, 4), 256>>>(x);
    winograd_fused<<<512, 256, FUSED_SMEM>>>(out);
}

// round 6
// speedup vs baseline: 1.2970x; 1.0939x over previous
#include <cuda_runtime.h>
#include <cuda_bf16.h>
#include <cstdint>

#define C_IN    64
#define K_OUT   64
#define H_IN    130
#define W_IN    130
#define H_OUT   128

// U in bf16 hi/lo (device globals: allocation-free rule)
__device__ __nv_bfloat16 g_Uh[36 * K_OUT * C_IN];   // [e][k][c]
__device__ __nv_bfloat16 g_Ul[36 * K_OUT * C_IN];

__device__ const float d_ATx[24] = {
    1.f, 1.f,  1.f, 1.f,  1.f, 0.f,
    0.f, 1.f, -1.f, 2.f, -2.f, 0.f,
    0.f, 1.f,  1.f, 4.f,  4.f, 0.f,
    0.f, 1.f, -1.f, 8.f, -8.f, 1.f};

__device__ __forceinline__ uint32_t smem_u32(const void* p) {
    uint32_t a;
    asm("{ .reg .u64 t; cvta.to.shared.u64 t, %1; cvt.u32.u64 %0, t; }"
        : "=r"(a) : "l"(p));
    return a;
}

#define LDSM4(r, a)                                                          \
    asm volatile("ldmatrix.sync.aligned.m8n8.x4.shared.b16 {%0,%1,%2,%3}, [%4];" \
                 : "=r"((r)[0]), "=r"((r)[1]), "=r"((r)[2]), "=r"((r)[3])    \
                 : "r"(a))
#define LDSM2(r, a)                                                          \
    asm volatile("ldmatrix.sync.aligned.m8n8.x2.shared.b16 {%0,%1}, [%2];"   \
                 : "=r"((r)[0]), "=r"((r)[1]) : "r"(a))

#define MMA_BF16(c, a, b0, b1)                                               \
    asm volatile("mma.sync.aligned.m16n8k16.row.col.f32.bf16.bf16.f32 "      \
                 "{%0,%1,%2,%3},{%4,%5,%6,%7},{%8,%9},{%0,%1,%2,%3};"        \
                 : "+f"((c)[0]), "+f"((c)[1]), "+f"((c)[2]), "+f"((c)[3])    \
                 : "r"((a)[0]), "r"((a)[1]), "r"((a)[2]), "r"((a)[3]),       \
                   "r"(b0), "r"(b1))

__device__ __forceinline__ void cp16(uint32_t dst, const void* src) {
    asm volatile("cp.async.cg.shared.global [%0], [%1], 16;" :: "r"(dst), "l"(src));
}
#define CP_COMMIT() asm volatile("cp.async.commit_group;" ::: "memory")
#define CP_WAIT(n)  asm volatile("cp.async.wait_group %0;" :: "n"(n) : "memory")

// ---------------------------------------------------------------------------
// Kernel 1: filter transform -> g_Uh/g_Ul bf16 [e][k][c]
// grid (64 k, 6 a) x 64 c threads; each thread writes 6 b-outputs.
// ---------------------------------------------------------------------------
__global__ void filter_transform(const float* __restrict__ w) {
    int c = threadIdx.x;
    int k = blockIdx.x;
    int a = blockIdx.y;

    constexpr float G[6][3] = {
        { 0.25f,     0.f,       0.f     },
        {-1.f/6.f,  -1.f/6.f,  -1.f/6.f },
        {-1.f/6.f,   1.f/6.f,  -1.f/6.f },
        { 1.f/24.f,  1.f/12.f,  1.f/6.f },
        { 1.f/24.f, -1.f/12.f,  1.f/6.f },
        { 0.f,       0.f,       1.f     }};

    const float* wp = w + (k * C_IN + c) * 9;
    float gw[3];
#pragma unroll
    for (int j = 0; j < 3; j++)
        gw[j] = G[a][0] * wp[0 * 3 + j] + G[a][1] * wp[1 * 3 + j] + G[a][2] * wp[2 * 3 + j];

#pragma unroll
    for (int b = 0; b < 6; b++) {
        float u = gw[0] * G[b][0] + gw[1] * G[b][1] + gw[2] * G[b][2];
        int idx = ((a * 6 + b) * K_OUT + k) * C_IN + c;
        __nv_bfloat16 h = __float2bfloat16_rn(u);
        g_Uh[idx] = h;
        g_Ul[idx] = __float2bfloat16_rn(u - __bfloat162float(h));
    }
}

// ---------------------------------------------------------------------------
// Kernel 2: fully fused — input transform + GEMM + output transform.
// CTA = half tile-row: 16 tiles (p) x 64 k, all 36 e.
// smem: V-all 36 x [hi 2K | lo 2K] = 144 KB, then U stages 3 x 16 KB = 48 KB.
// ---------------------------------------------------------------------------
#define VALL_SZ   147456u
#define USTAGE_SZ 16384u
#define FUSED_SMEM (147456u + 3u * 16384u)   /* 196608 B */

__device__ __forceinline__ void issue_U(int e, uint32_t buf, int tid) {
#pragma unroll
    for (int i = 0; i < 2; i++) {
        int id = tid + i * 256;           // 0..511
        int r = id >> 3, c8 = id & 7;     // r = k row, c8 = 16B chunk
        uint32_t off = (uint32_t)(r * 128) + ((uint32_t)(c8 ^ (r & 7)) << 4);
        cp16(buf + off,         g_Uh + (size_t)e * 4096 + r * 64 + c8 * 8);
        cp16(buf + 8192u + off, g_Ul + (size_t)e * 4096 + r * 64 + c8 * 8);
    }
}

__global__ __launch_bounds__(256, 1) void winograd_fused(
        float* __restrict__ out, const float* __restrict__ x) {
    extern __shared__ __align__(128) char smem[];
    const uint32_t sb = smem_u32(smem);
    const uint32_t ub = sb + VALL_SZ;
    const int tid = threadIdx.x;
    const int lane = tid & 31;
    const int wn = tid >> 5;          // warp -> 8k slice
    const int bx = blockIdx.x;        // 1024 = 16n x 32t x 2h
    const int n = bx >> 6;
    const int t = (bx >> 1) & 31;
    const int h = bx & 1;

    // prefetch first two U stages while we do the input transform
    issue_U(0, ub, tid);                 CP_COMMIT();
    issue_U(1, ub + USTAGE_SZ, tid);     CP_COMMIT();

    // ---- phase 1: input transform for 16 tiles x 64 c -> V-all smem ----
    constexpr float BT[6][6] = {
        {4.f, 0.f, -5.f,  0.f, 1.f, 0.f},
        {0.f,-4.f, -4.f,  1.f, 1.f, 0.f},
        {0.f, 4.f, -4.f, -1.f, 1.f, 0.f},
        {0.f,-2.f, -1.f,  2.f, 1.f, 0.f},
        {0.f, 2.f, -1.f, -2.f, 1.f, 0.f},
        {0.f, 4.f,  0.f, -5.f, 0.f, 1.f}};

#pragma unroll
    for (int iter = 0; iter < 4; iter++) {
        int p_l = tid & 15;                       // tile within half-row
        int c   = iter * 16 + (tid >> 4);
        const float* xb = x + ((size_t)(n * C_IN + c) * H_IN + 4 * t) * W_IN
                            + (h * 16 + p_l) * 4;
        float d[6][6];
#pragma unroll
        for (int i = 0; i < 6; i++) {
            float2 v0 = *(const float2*)(xb + i * W_IN + 0);
            float2 v1 = *(const float2*)(xb + i * W_IN + 2);
            float2 v2 = *(const float2*)(xb + i * W_IN + 4);
            d[i][0] = v0.x; d[i][1] = v0.y;
            d[i][2] = v1.x; d[i][3] = v1.y;
            d[i][4] = v2.x; d[i][5] = v2.y;
        }
        float t1[6][6];
#pragma unroll
        for (int a = 0; a < 6; a++)
#pragma unroll
            for (int j = 0; j < 6; j++) {
                float acc = 0.f;
#pragma unroll
                for (int i = 0; i < 6; i++) acc += BT[a][i] * d[i][j];
                t1[a][j] = acc;
            }
        uint32_t swb = (uint32_t)(p_l * 128)
                     + ((uint32_t)((c >> 3) ^ (p_l & 7)) << 4) + (c & 7) * 2;
#pragma unroll
        for (int a = 0; a < 6; a++)
#pragma unroll
            for (int b = 0; b < 6; b++) {
                float v = 0.f;
#pragma unroll
                for (int j = 0; j < 6; j++) v += t1[a][j] * BT[b][j];
                __nv_bfloat16 hi = __float2bfloat16_rn(v);
                __nv_bfloat16 lo = __float2bfloat16_rn(v - __bfloat162float(hi));
                uint32_t base = (uint32_t)(a * 6 + b) * 4096u + swb;
                *(__nv_bfloat16*)(smem + base)         = hi;
                *(__nv_bfloat16*)(smem + base + 2048u) = lo;
            }
    }

    // ---- phase 2: 36-stage MMA + fused output transform ----
    float Y[4][4][4];
#pragma unroll
    for (int xx = 0; xx < 4; xx++)
#pragma unroll
        for (int q = 0; q < 4; q++)
#pragma unroll
            for (int y = 0; y < 4; y++) Y[xx][q][y] = 0.f;

    constexpr float ATC[4][6] = {
        {1.f, 1.f,  1.f, 1.f,  1.f, 0.f},
        {0.f, 1.f, -1.f, 2.f, -2.f, 0.f},
        {0.f, 1.f,  1.f, 4.f,  4.f, 0.f},
        {0.f, 1.f, -1.f, 8.f, -8.f, 1.f}};

    for (int a = 0; a < 6; a++) {
        float Z[4][4];
#pragma unroll
        for (int q = 0; q < 4; q++)
#pragma unroll
            for (int y = 0; y < 4; y++) Z[q][y] = 0.f;

#pragma unroll
        for (int b = 0; b < 6; b++) {
            CP_WAIT(1);
            __syncthreads();
            const int e = a * 6 + b;
            if (e + 2 < 36)
                issue_U(e + 2, ub + (uint32_t)((b + 2) % 3) * USTAGE_SZ, tid);
            CP_COMMIT();

            const uint32_t ust = ub + (uint32_t)(b % 3) * USTAGE_SZ;
            const uint32_t va  = sb + (uint32_t)e * 4096u;

            float acc[4] = {0.f, 0.f, 0.f, 0.f};
#pragma unroll
            for (int ks = 0; ks < 4; ks++) {
                uint32_t Ah[4], Al[4], bh[2], bl[2];
                int rowA = lane & 15;
                int colA = (ks * 2 + (lane >> 4)) ^ (rowA & 7);
                uint32_t aA = va + (uint32_t)(rowA * 128 + colA * 16);
                LDSM4(Ah, aA);
                LDSM4(Al, aA + 2048u);
                int rowB = wn * 8 + (lane & 7);
                int colB = (ks * 2 + ((lane >> 3) & 1)) ^ (rowB & 7);
                uint32_t aB = ust + (uint32_t)(rowB * 128 + colB * 16);
                LDSM2(bh, aB);
                LDSM2(bl, aB + 8192u);
                MMA_BF16(acc, Ah, bh[0], bh[1]);   // hi*hi
                MMA_BF16(acc, Ah, bl[0], bl[1]);   // hi*lo
                MMA_BF16(acc, Al, bh[0], bh[1]);   // lo*hi
            }
#pragma unroll
            for (int q = 0; q < 4; q++)
#pragma unroll
                for (int y = 0; y < 4; y++)
                    Z[q][y] += ATC[y][b] * acc[q];
        }

        float cx0 = d_ATx[a], cx1 = d_ATx[6 + a], cx2 = d_ATx[12 + a], cx3 = d_ATx[18 + a];
#pragma unroll
        for (int q = 0; q < 4; q++)
#pragma unroll
            for (int y = 0; y < 4; y++) {
                float z = Z[q][y];
                Y[0][q][y] += cx0 * z;
                Y[1][q][y] += cx1 * z;
                Y[2][q][y] += cx2 * z;
                Y[3][q][y] += cx3 * z;
            }
    }

    // ---- epilogue: direct stores ----
    const int k0   = wn * 8 + (lane & 3) * 2;
    const int s_lo = lane >> 2;
#pragma unroll
    for (int q = 0; q < 4; q++) {
        int s = h * 16 + s_lo + ((q >> 1) << 3);
        int k = k0 + (q & 1);
        float* ob = out + ((size_t)(n * K_OUT + k) * H_OUT + t * 4) * H_OUT + s * 4;
#pragma unroll
        for (int xx = 0; xx < 4; xx++) {
            float4 v = make_float4(Y[xx][q][0], Y[xx][q][1], Y[xx][q][2], Y[xx][q][3]);
            *(float4*)&ob[(size_t)xx * H_OUT] = v;
        }
    }
}

// ---------------------------------------------------------------------------
extern "C" void kernel_launch(void* const* d_in, const int* in_sizes, int n_in,
                              void* d_out, int out_size) {
    const float* x = (const float*)d_in[0];   // (16,64,130,130)
    const float* w = (const float*)d_in[1];   // (64,64,3,3)
    float* out = (float*)d_out;               // (16,64,128,128)

    cudaFuncSetAttribute(winograd_fused,
                         cudaFuncAttributeMaxDynamicSharedMemorySize, FUSED_SMEM);

    filter_transform<<<dim3(64, 6), 64>>>(w);
    winograd_fused<<<1024, 256, FUSED_SMEM>>>(out, x);
}

// round 7
// speedup vs baseline: 1.3315x; 1.0266x over previous
#include <cuda_runtime.h>
#include <cuda_bf16.h>
#include <cstdint>

#define C_IN    64
#define K_OUT   64
#define H_IN    130
#define W_IN    130
#define H_OUT   128

// U in bf16 hi/lo (device globals: allocation-free rule)
__device__ __nv_bfloat16 g_Uh[36 * K_OUT * C_IN];   // [e][k][c]
__device__ __nv_bfloat16 g_Ul[36 * K_OUT * C_IN];

__device__ const float d_ATx[24] = {
    1.f, 1.f,  1.f, 1.f,  1.f, 0.f,
    0.f, 1.f, -1.f, 2.f, -2.f, 0.f,
    0.f, 1.f,  1.f, 4.f,  4.f, 0.f,
    0.f, 1.f, -1.f, 8.f, -8.f, 1.f};

__device__ __forceinline__ uint32_t smem_u32(const void* p) {
    uint32_t a;
    asm("{ .reg .u64 t; cvta.to.shared.u64 t, %1; cvt.u32.u64 %0, t; }"
        : "=r"(a) : "l"(p));
    return a;
}

#define LDSM4(r, a)                                                          \
    asm volatile("ldmatrix.sync.aligned.m8n8.x4.shared.b16 {%0,%1,%2,%3}, [%4];" \
                 : "=r"((r)[0]), "=r"((r)[1]), "=r"((r)[2]), "=r"((r)[3])    \
                 : "r"(a))
#define LDSM2(r, a)                                                          \
    asm volatile("ldmatrix.sync.aligned.m8n8.x2.shared.b16 {%0,%1}, [%2];"   \
                 : "=r"((r)[0]), "=r"((r)[1]) : "r"(a))

#define MMA_BF16(c, a, b0, b1)                                               \
    asm volatile("mma.sync.aligned.m16n8k16.row.col.f32.bf16.bf16.f32 "      \
                 "{%0,%1,%2,%3},{%4,%5,%6,%7},{%8,%9},{%0,%1,%2,%3};"        \
                 : "+f"((c)[0]), "+f"((c)[1]), "+f"((c)[2]), "+f"((c)[3])    \
                 : "r"((a)[0]), "r"((a)[1]), "r"((a)[2]), "r"((a)[3]),       \
                   "r"(b0), "r"(b1))

__device__ __forceinline__ void cp16(uint32_t dst, const void* src) {
    asm volatile("cp.async.cg.shared.global [%0], [%1], 16;" :: "r"(dst), "l"(src));
}
#define CP_COMMIT() asm volatile("cp.async.commit_group;" ::: "memory")
#define CP_WAIT(n)  asm volatile("cp.async.wait_group %0;" :: "n"(n) : "memory")

// ---------------------------------------------------------------------------
// Kernel 1: filter transform -> g_Uh/g_Ul bf16 [e][k][c]
// ---------------------------------------------------------------------------
__global__ void filter_transform(const float* __restrict__ w) {
    int c = threadIdx.x;
    int k = blockIdx.x;
    int a = blockIdx.y;

    constexpr float G[6][3] = {
        { 0.25f,     0.f,       0.f     },
        {-1.f/6.f,  -1.f/6.f,  -1.f/6.f },
        {-1.f/6.f,   1.f/6.f,  -1.f/6.f },
        { 1.f/24.f,  1.f/12.f,  1.f/6.f },
        { 1.f/24.f, -1.f/12.f,  1.f/6.f },
        { 0.f,       0.f,       1.f     }};

    const float* wp = w + (k * C_IN + c) * 9;
    float gw[3];
#pragma unroll
    for (int j = 0; j < 3; j++)
        gw[j] = G[a][0] * wp[0 * 3 + j] + G[a][1] * wp[1 * 3 + j] + G[a][2] * wp[2 * 3 + j];

#pragma unroll
    for (int b = 0; b < 6; b++) {
        float u = gw[0] * G[b][0] + gw[1] * G[b][1] + gw[2] * G[b][2];
        int idx = ((a * 6 + b) * K_OUT + k) * C_IN + c;
        __nv_bfloat16 h = __float2bfloat16_rn(u);
        g_Uh[idx] = h;
        g_Ul[idx] = __float2bfloat16_rn(u - __bfloat162float(h));
    }
}

// ---------------------------------------------------------------------------
// Kernel 2: fully fused — input transform + GEMM + output transform.
// CTA = half tile-row: 16 tiles (p) x 64 k, all 36 e.
// smem: V-all 36 x [hi 2K | lo 2K] = 144 KB, then 4 U buffers x 16 KB.
// Mainloop is barrier-free: each warp streams its OWN 8 k-rows of U via
// cp.async (warp-local wait_group); V is resident; slices are disjoint.
// ---------------------------------------------------------------------------
#define VALL_SZ   147456u
#define USTAGE_SZ 16384u
#define FUSED_SMEM (147456u + 4u * 16384u)   /* 212992 B */

// per-warp slice: rows wn*8 .. wn*8+7 (hi & lo), 4 cp16 per lane
__device__ __forceinline__ void issue_U_warp(int e, uint32_t buf, int wn, int lane) {
#pragma unroll
    for (int i = 0; i < 2; i++) {
        int idx = lane + 32 * i;            // 0..63
        int rl = idx >> 3, c8 = idx & 7;    // row-local, 16B chunk
        int r = wn * 8 + rl;
        uint32_t off = (uint32_t)(r * 128) + ((uint32_t)(c8 ^ (r & 7)) << 4);
        cp16(buf + off,         g_Uh + (size_t)e * 4096 + r * 64 + c8 * 8);
        cp16(buf + 8192u + off, g_Ul + (size_t)e * 4096 + r * 64 + c8 * 8);
    }
}

__global__ __launch_bounds__(256, 1) void winograd_fused(
        float* __restrict__ out, const float* __restrict__ x) {
    extern __shared__ __align__(128) char smem[];
    const uint32_t sb = smem_u32(smem);
    const uint32_t ub = sb + VALL_SZ;
    const int tid = threadIdx.x;
    const int lane = tid & 31;
    const int wn = tid >> 5;          // warp -> 8k slice
    const int bx = blockIdx.x;        // 1024 = 16n x 32t x 2h
    const int n = bx >> 6;
    const int t = (bx >> 1) & 31;
    const int h = bx & 1;

    // prefetch U stages 0,1 (own slice only)
    issue_U_warp(0, ub, wn, lane);              CP_COMMIT();
    issue_U_warp(1, ub + USTAGE_SZ, wn, lane);  CP_COMMIT();

    // ---- phase 1: input transform for 16 tiles x 64 c -> V-all smem ----
    constexpr float BT[6][6] = {
        {4.f, 0.f, -5.f,  0.f, 1.f, 0.f},
        {0.f,-4.f, -4.f,  1.f, 1.f, 0.f},
        {0.f, 4.f, -4.f, -1.f, 1.f, 0.f},
        {0.f,-2.f, -1.f,  2.f, 1.f, 0.f},
        {0.f, 2.f, -1.f, -2.f, 1.f, 0.f},
        {0.f, 4.f,  0.f, -5.f, 0.f, 1.f}};

#pragma unroll
    for (int iter = 0; iter < 4; iter++) {
        int p_l = tid & 15;                       // tile within half-row
        int c   = iter * 16 + (tid >> 4);
        const float* xb = x + ((size_t)(n * C_IN + c) * H_IN + 4 * t) * W_IN
                            + (h * 16 + p_l) * 4;
        float d[6][6];
#pragma unroll
        for (int i = 0; i < 6; i++) {
            float2 v0 = *(const float2*)(xb + i * W_IN + 0);
            float2 v1 = *(const float2*)(xb + i * W_IN + 2);
            float2 v2 = *(const float2*)(xb + i * W_IN + 4);
            d[i][0] = v0.x; d[i][1] = v0.y;
            d[i][2] = v1.x; d[i][3] = v1.y;
            d[i][4] = v2.x; d[i][5] = v2.y;
        }
        float t1[6][6];
#pragma unroll
        for (int a = 0; a < 6; a++)
#pragma unroll
            for (int j = 0; j < 6; j++) {
                float acc = 0.f;
#pragma unroll
                for (int i = 0; i < 6; i++) acc += BT[a][i] * d[i][j];
                t1[a][j] = acc;
            }
        uint32_t swb = (uint32_t)(p_l * 128)
                     + ((uint32_t)((c >> 3) ^ (p_l & 7)) << 4) + (c & 7) * 2;
#pragma unroll
        for (int a = 0; a < 6; a++)
#pragma unroll
            for (int b = 0; b < 6; b++) {
                float v = 0.f;
#pragma unroll
                for (int j = 0; j < 6; j++) v += t1[a][j] * BT[b][j];
                __nv_bfloat16 hi = __float2bfloat16_rn(v);
                __nv_bfloat16 lo = __float2bfloat16_rn(v - __bfloat162float(hi));
                uint32_t base = (uint32_t)(a * 6 + b) * 4096u + swb;
                *(__nv_bfloat16*)(smem + base)         = hi;
                *(__nv_bfloat16*)(smem + base + 2048u) = lo;
            }
    }
    __syncthreads();   // the ONLY barrier: V must be complete before MMA

    // ---- phase 2: 36-stage barrier-free MMA + fused output transform ----
    float Y[4][4][4];
#pragma unroll
    for (int xx = 0; xx < 4; xx++)
#pragma unroll
        for (int q = 0; q < 4; q++)
#pragma unroll
            for (int y = 0; y < 4; y++) Y[xx][q][y] = 0.f;

    constexpr float ATC[4][6] = {
        {1.f, 1.f,  1.f, 1.f,  1.f, 0.f},
        {0.f, 1.f, -1.f, 2.f, -2.f, 0.f},
        {0.f, 1.f,  1.f, 4.f,  4.f, 0.f},
        {0.f, 1.f, -1.f, 8.f, -8.f, 1.f}};

    for (int a = 0; a < 6; a++) {
        float Z[4][4];
#pragma unroll
        for (int q = 0; q < 4; q++)
#pragma unroll
            for (int y = 0; y < 4; y++) Z[q][y] = 0.f;

#pragma unroll
        for (int b = 0; b < 6; b++) {
            const int e = a * 6 + b;
            CP_WAIT(1);                         // warp-local: stage e ready
            if (e + 2 < 36)
                issue_U_warp(e + 2, ub + (uint32_t)((e + 2) & 3) * USTAGE_SZ, wn, lane);
            CP_COMMIT();

            const uint32_t ust = ub + (uint32_t)(e & 3) * USTAGE_SZ;
            const uint32_t va  = sb + (uint32_t)e * 4096u;

            float acc[4] = {0.f, 0.f, 0.f, 0.f};
#pragma unroll
            for (int ks = 0; ks < 4; ks++) {
                uint32_t Ah[4], Al[4], bh[2], bl[2];
                int rowA = lane & 15;
                int colA = (ks * 2 + (lane >> 4)) ^ (rowA & 7);
                uint32_t aA = va + (uint32_t)(rowA * 128 + colA * 16);
                LDSM4(Ah, aA);
                LDSM4(Al, aA + 2048u);
                int rowB = wn * 8 + (lane & 7);
                int colB = (ks * 2 + ((lane >> 3) & 1)) ^ (rowB & 7);
                uint32_t aB = ust + (uint32_t)(rowB * 128 + colB * 16);
                LDSM2(bh, aB);
                LDSM2(bl, aB + 8192u);
                MMA_BF16(acc, Ah, bh[0], bh[1]);   // hi*hi
                MMA_BF16(acc, Ah, bl[0], bl[1]);   // hi*lo
                MMA_BF16(acc, Al, bh[0], bh[1]);   // lo*hi
            }
#pragma unroll
            for (int q = 0; q < 4; q++)
#pragma unroll
                for (int y = 0; y < 4; y++)
                    Z[q][y] += ATC[y][b] * acc[q];
        }

        float cx0 = d_ATx[a], cx1 = d_ATx[6 + a], cx2 = d_ATx[12 + a], cx3 = d_ATx[18 + a];
#pragma unroll
        for (int q = 0; q < 4; q++)
#pragma unroll
            for (int y = 0; y < 4; y++) {
                float z = Z[q][y];
                Y[0][q][y] += cx0 * z;
                Y[1][q][y] += cx1 * z;
                Y[2][q][y] += cx2 * z;
                Y[3][q][y] += cx3 * z;
            }
    }

    // ---- epilogue: direct stores ----
    const int k0   = wn * 8 + (lane & 3) * 2;
    const int s_lo = lane >> 2;
#pragma unroll
    for (int q = 0; q < 4; q++) {
        int s = h * 16 + s_lo + ((q >> 1) << 3);
        int k = k0 + (q & 1);
        float* ob = out + ((size_t)(n * K_OUT + k) * H_OUT + t * 4) * H_OUT + s * 4;
#pragma unroll
        for (int xx = 0; xx < 4; xx++) {
            float4 v = make_float4(Y[xx][q][0], Y[xx][q][1], Y[xx][q][2], Y[xx][q][3]);
            *(float4*)&ob[(size_t)xx * H_OUT] = v;
        }
    }
}

// ---------------------------------------------------------------------------
extern "C" void kernel_launch(void* const* d_in, const int* in_sizes, int n_in,
                              void* d_out, int out_size) {
    const float* x = (const float*)d_in[0];   // (16,64,130,130)
    const float* w = (const float*)d_in[1];   // (64,64,3,3)
    float* out = (float*)d_out;               // (16,64,128,128)

    cudaFuncSetAttribute(winograd_fused,
                         cudaFuncAttributeMaxDynamicSharedMemorySize, FUSED_SMEM);

    filter_transform<<<dim3(64, 6), 64>>>(w);
    winograd_fused<<<1024, 256, FUSED_SMEM>>>(out, x);
}

// round 8
// speedup vs baseline: 1.6232x; 1.2190x over previous
#include <cuda_runtime.h>
#include <cuda_bf16.h>
#include <cstdint>

#define C_IN    64
#define K_OUT   64
#define H_IN    130
#define W_IN    130
#define H_OUT   128

// U in mma.sync B-fragment order: uint4 per (e, kslice, ks, lane) = {b0h,b1h,b0l,b1l}
__device__ uint4 g_Ufrag[36 * 8 * 4 * 32];   // 589 KB

__device__ const float d_ATx[24] = {
    1.f, 1.f,  1.f, 1.f,  1.f, 0.f,
    0.f, 1.f, -1.f, 2.f, -2.f, 0.f,
    0.f, 1.f,  1.f, 4.f,  4.f, 0.f,
    0.f, 1.f, -1.f, 8.f, -8.f, 1.f};

__device__ __forceinline__ uint32_t smem_u32(const void* p) {
    uint32_t a;
    asm("{ .reg .u64 t; cvta.to.shared.u64 t, %1; cvt.u32.u64 %0, t; }"
        : "=r"(a) : "l"(p));
    return a;
}

#define LDSM4(r, a)                                                          \
    asm volatile("ldmatrix.sync.aligned.m8n8.x4.shared.b16 {%0,%1,%2,%3}, [%4];" \
                 : "=r"((r)[0]), "=r"((r)[1]), "=r"((r)[2]), "=r"((r)[3])    \
                 : "r"(a))

#define MMA_BF16(c, a, b0, b1)                                               \
    asm volatile("mma.sync.aligned.m16n8k16.row.col.f32.bf16.bf16.f32 "      \
                 "{%0,%1,%2,%3},{%4,%5,%6,%7},{%8,%9},{%0,%1,%2,%3};"        \
                 : "+f"((c)[0]), "+f"((c)[1]), "+f"((c)[2]), "+f"((c)[3])    \
                 : "r"((a)[0]), "r"((a)[1]), "r"((a)[2]), "r"((a)[3]),       \
                   "r"(b0), "r"(b1))

// ---------------------------------------------------------------------------
// Kernel 1: filter transform -> g_Ufrag (fragment-order, hi/lo split)
// grid (64 k, 6 a) x 64 c threads
// ---------------------------------------------------------------------------
__global__ void filter_transform(const float* __restrict__ w) {
    int c = threadIdx.x;
    int k = blockIdx.x;
    int a = blockIdx.y;

    constexpr float G[6][3] = {
        { 0.25f,     0.f,       0.f     },
        {-1.f/6.f,  -1.f/6.f,  -1.f/6.f },
        {-1.f/6.f,   1.f/6.f,  -1.f/6.f },
        { 1.f/24.f,  1.f/12.f,  1.f/6.f },
        { 1.f/24.f, -1.f/12.f,  1.f/6.f },
        { 0.f,       0.f,       1.f     }};

    const float* wp = w + (k * C_IN + c) * 9;
    float gw[3];
#pragma unroll
    for (int j = 0; j < 3; j++)
        gw[j] = G[a][0] * wp[0 * 3 + j] + G[a][1] * wp[1 * 3 + j] + G[a][2] * wp[2 * 3 + j];

    // fragment coordinates for this (k, c)
    int wsl = k >> 3;
    int l   = (k & 7) * 4 + ((c & 7) >> 1);
    int ks  = c >> 4;
    int hh  = (c >> 3) & 1;      // selects b0 vs b1
    int dd  = c & 1;             // low/high half of bf16x2
    unsigned short* ub = (unsigned short*)g_Ufrag;

#pragma unroll
    for (int b = 0; b < 6; b++) {
        float u = gw[0] * G[b][0] + gw[1] * G[b][1] + gw[2] * G[b][2];
        int e = a * 6 + b;
        size_t u4 = ((size_t)(e * 8 + wsl) * 4 + ks) * 32 + l;
        __nv_bfloat16 hi = __float2bfloat16_rn(u);
        __nv_bfloat16 lo = __float2bfloat16_rn(u - __bfloat162float(hi));
        ub[u4 * 8 + hh * 2 + dd]     = *(unsigned short*)&hi;
        ub[u4 * 8 + 4 + hh * 2 + dd] = *(unsigned short*)&lo;
    }
}

// ---------------------------------------------------------------------------
// Kernel 2: fully fused — input transform + GEMM + output transform.
// CTA = half tile-row: 16 tiles (p) x 64 k, all 36 e.
// smem: V-all only, 36 x [hi 2K | lo 2K] = 144 KB.
// U comes straight from gmem (L2-hot) into registers, prefetch depth 2.
// ---------------------------------------------------------------------------
#define FUSED_SMEM 147456u

__global__ __launch_bounds__(256, 1) void winograd_fused(
        float* __restrict__ out, const float* __restrict__ x) {
    extern __shared__ __align__(128) char smem[];
    const uint32_t sb = smem_u32(smem);
    const int tid = threadIdx.x;
    const int lane = tid & 31;
    const int wn = tid >> 5;          // warp -> 8k slice
    const int bx = blockIdx.x;        // 1024 = 16n x 32t x 2h
    const int n = bx >> 6;
    const int t = (bx >> 1) & 31;
    const int h = bx & 1;

    // B-fragment ring (3 bufs; e % 3 == b % 3 since 6 % 3 == 0)
    uint4 Bf[3][4];
    const uint4* Ub = g_Ufrag;
#pragma unroll
    for (int ks = 0; ks < 4; ks++)
        Bf[0][ks] = __ldg(&Ub[((0 * 8 + wn) * 4 + ks) * 32 + lane]);
#pragma unroll
    for (int ks = 0; ks < 4; ks++)
        Bf[1][ks] = __ldg(&Ub[((1 * 8 + wn) * 4 + ks) * 32 + lane]);

    // ---- phase 1: input transform, c-pairs, bf16x2 packed stores ----
    constexpr float BT[6][6] = {
        {4.f, 0.f, -5.f,  0.f, 1.f, 0.f},
        {0.f,-4.f, -4.f,  1.f, 1.f, 0.f},
        {0.f, 4.f, -4.f, -1.f, 1.f, 0.f},
        {0.f,-2.f, -1.f,  2.f, 1.f, 0.f},
        {0.f, 2.f, -1.f, -2.f, 1.f, 0.f},
        {0.f, 4.f,  0.f, -5.f, 0.f, 1.f}};

#pragma unroll
    for (int iter = 0; iter < 2; iter++) {
        int p_l = tid & 15;
        int c0  = iter * 32 + (tid >> 4) * 2;
        const float* xb0 = x + ((size_t)(n * C_IN + c0) * H_IN + 4 * t) * W_IN
                             + (h * 16 + p_l) * 4;
        const float* xb1 = xb0 + (size_t)H_IN * W_IN;

        float t10[6][6], t11[6][6];
#pragma unroll
        for (int half = 0; half < 2; half++) {
            const float* xb = half ? xb1 : xb0;
            float d[6][6];
#pragma unroll
            for (int i = 0; i < 6; i++) {
                float2 v0 = *(const float2*)(xb + i * W_IN + 0);
                float2 v1 = *(const float2*)(xb + i * W_IN + 2);
                float2 v2 = *(const float2*)(xb + i * W_IN + 4);
                d[i][0] = v0.x; d[i][1] = v0.y;
                d[i][2] = v1.x; d[i][3] = v1.y;
                d[i][4] = v2.x; d[i][5] = v2.y;
            }
            float (*t1)[6] = half ? t11 : t10;
#pragma unroll
            for (int a = 0; a < 6; a++)
#pragma unroll
                for (int j = 0; j < 6; j++) {
                    float acc = 0.f;
#pragma unroll
                    for (int i = 0; i < 6; i++) acc += BT[a][i] * d[i][j];
                    t1[a][j] = acc;
                }
        }

        uint32_t swb = (uint32_t)(p_l * 128)
                     + ((uint32_t)((c0 >> 3) ^ (p_l & 7)) << 4) + (c0 & 7) * 2;
#pragma unroll
        for (int a = 0; a < 6; a++)
#pragma unroll
            for (int b = 0; b < 6; b++) {
                float v0 = 0.f, v1 = 0.f;
#pragma unroll
                for (int j = 0; j < 6; j++) {
                    v0 += t10[a][j] * BT[b][j];
                    v1 += t11[a][j] * BT[b][j];
                }
                float h0 = __bfloat162float(__float2bfloat16_rn(v0));
                float h1 = __bfloat162float(__float2bfloat16_rn(v1));
                uint32_t base = (uint32_t)(a * 6 + b) * 4096u + swb;
                *(__nv_bfloat162*)(smem + base) = __floats2bfloat162_rn(v0, v1);
                *(__nv_bfloat162*)(smem + base + 2048u) =
                    __floats2bfloat162_rn(v0 - h0, v1 - h1);
            }
    }
    __syncthreads();   // V complete; mainloop is barrier-free

    // ---- phase 2: 36-stage MMA + fused output transform ----
    float Y[4][4][4];
#pragma unroll
    for (int xx = 0; xx < 4; xx++)
#pragma unroll
        for (int q = 0; q < 4; q++)
#pragma unroll
            for (int y = 0; y < 4; y++) Y[xx][q][y] = 0.f;

    constexpr float ATC[4][6] = {
        {1.f, 1.f,  1.f, 1.f,  1.f, 0.f},
        {0.f, 1.f, -1.f, 2.f, -2.f, 0.f},
        {0.f, 1.f,  1.f, 4.f,  4.f, 0.f},
        {0.f, 1.f, -1.f, 8.f, -8.f, 1.f}};

    for (int a = 0; a < 6; a++) {
        float Z[4][4];
#pragma unroll
        for (int q = 0; q < 4; q++)
#pragma unroll
            for (int y = 0; y < 4; y++) Z[q][y] = 0.f;

#pragma unroll
        for (int b = 0; b < 6; b++) {
            const int e = a * 6 + b;
            // prefetch stage e+2 into ring slot (b+2)%3 (holds e-1, consumed)
            if (e + 2 < 36) {
#pragma unroll
                for (int ks = 0; ks < 4; ks++)
                    Bf[(b + 2) % 3][ks] =
                        __ldg(&Ub[(((e + 2) * 8 + wn) * 4 + ks) * 32 + lane]);
            }

            const uint32_t va = sb + (uint32_t)e * 4096u;
            float acc[4] = {0.f, 0.f, 0.f, 0.f};
#pragma unroll
            for (int ks = 0; ks < 4; ks++) {
                uint32_t Ah[4], Al[4];
                int rowA = lane & 15;
                int colA = (ks * 2 + (lane >> 4)) ^ (rowA & 7);
                uint32_t aA = va + (uint32_t)(rowA * 128 + colA * 16);
                LDSM4(Ah, aA);
                LDSM4(Al, aA + 2048u);
                const uint4 B = Bf[b % 3][ks];
                MMA_BF16(acc, Ah, B.x, B.y);   // hi*hi
                MMA_BF16(acc, Ah, B.z, B.w);   // hi*lo
                MMA_BF16(acc, Al, B.x, B.y);   // lo*hi
            }
#pragma unroll
            for (int q = 0; q < 4; q++)
#pragma unroll
                for (int y = 0; y < 4; y++)
                    Z[q][y] += ATC[y][b] * acc[q];
        }

        float cx0 = d_ATx[a], cx1 = d_ATx[6 + a], cx2 = d_ATx[12 + a], cx3 = d_ATx[18 + a];
#pragma unroll
        for (int q = 0; q < 4; q++)
#pragma unroll
            for (int y = 0; y < 4; y++) {
                float z = Z[q][y];
                Y[0][q][y] += cx0 * z;
                Y[1][q][y] += cx1 * z;
                Y[2][q][y] += cx2 * z;
                Y[3][q][y] += cx3 * z;
            }
    }

    // ---- epilogue: direct stores ----
    const int k0   = wn * 8 + (lane & 3) * 2;
    const int s_lo = lane >> 2;
#pragma unroll
    for (int q = 0; q < 4; q++) {
        int s = h * 16 + s_lo + ((q >> 1) << 3);
        int k = k0 + (q & 1);
        float* ob = out + ((size_t)(n * K_OUT + k) * H_OUT + t * 4) * H_OUT + s * 4;
#pragma unroll
        for (int xx = 0; xx < 4; xx++) {
            float4 v = make_float4(Y[xx][q][0], Y[xx][q][1], Y[xx][q][2], Y[xx][q][3]);
            *(float4*)&ob[(size_t)xx * H_OUT] = v;
        }
    }
}

// ---------------------------------------------------------------------------
extern "C" void kernel_launch(void* const* d_in, const int* in_sizes, int n_in,
                              void* d_out, int out_size) {
    const float* x = (const float*)d_in[0];   // (16,64,130,130)
    const float* w = (const float*)d_in[1];   // (64,64,3,3)
    float* out = (float*)d_out;               // (16,64,128,128)

    cudaFuncSetAttribute(winograd_fused,
                         cudaFuncAttributeMaxDynamicSharedMemorySize, FUSED_SMEM);

    filter_transform<<<dim3(64, 6), 64>>>(w);
    winograd_fused<<<1024, 256, FUSED_SMEM>>>(out, x);
}